// round 16
// baseline (speedup 1.0000x reference)
#include <cuda_runtime.h>
#include <cuda_fp16.h>
#include <stdint.h>

// ---------------- problem constants ----------------
#define N_PATCH   40000
#define GRP       4
#define DIM       400          // 16*5*5
#define KC        64
#define EPOCHS    10
#define ROWSTRIDE 1600         // GRP*DIM floats per patch row
#define TM        256          // patches per tile (MMA M)
#define KPADP     208
#define NCH       13           // chunks of 32 k (16 pairs)
#define TILES_G   157          // ceil(40000/256)
#define CTAS_X    37           // persistent: 37*4 = 148 CTAs = 1 wave
#define THREADS   512
#define LSCALE    2048.0f      // low-plane scale 2^11
#define LINV      4.8828125e-4f

// fused-kernel smem layout (double-buffered staging)
#define APW    20              // pair-slots per row (16 + 4 pad) in uint32
#define APL2   (256*APW)       // 5120 u32 per A plane
#define BPL2   (64*APW)        // 1280 u32 per B plane
#define ABUFS  (2*APL2)        // one A buffer (2 planes) = 10240
#define BBUFS  (2*BPL2)        // one B buffer (2 planes) = 2560
#define STG_F  (2*ABUFS + 2*BBUFS)     // 25600 u32 (>= Cs 256*65=16640)
#define ACC_F  STG_F
#define CNT_F  (ACC_F + KC*DIM)        // 51200
#define LBL_F  (CNT_F + KC)            // 51264
#define C2_F   (LBL_F + TM)            // 51520
#define FUSED_F (C2_F + KC)            // 51584 floats
#define FUSED_SMEM (FUSED_F * 4)       // 206,336 B -> 1 CTA/SM

// ---------------- device state ----------------
__device__ float g_centroids[GRP * KC * DIM];
__device__ float g_c2[GRP * KC];
__device__ __align__(16) float g_sums[GRP * KC * DIM];
__device__ float g_counts[GRP * KC];
// centroid fp16-pair-packed planes (h, l'=l*2^11)
__device__ __align__(16) uint32_t g_cbp[GRP][2][KC][KPADP];

// ---------------- fp16 split helpers ----------------
__device__ __forceinline__ void split2h(float x, uint32_t& h, uint32_t& l) {
    __half hh = __float2half_rn(x);
    float r = x - __half2float(hh);
    __half ll = __float2half_rn(r * LSCALE);
    h = (uint32_t)__half_as_ushort(hh);
    l = (uint32_t)__half_as_ushort(ll);
}
__device__ __forceinline__ uint32_t pack2(uint32_t a, uint32_t b) {
    return a | (b << 16);
}
__device__ __forceinline__ void mma_f16(float* c, const uint32_t* a,
                                        uint32_t b0, uint32_t b1) {
    asm volatile(
        "mma.sync.aligned.m16n8k16.row.col.f32.f16.f16.f32 "
        "{%0,%1,%2,%3}, {%4,%5,%6,%7}, {%8,%9}, {%0,%1,%2,%3};"
        : "+f"(c[0]), "+f"(c[1]), "+f"(c[2]), "+f"(c[3])
        : "r"(a[0]), "r"(a[1]), "r"(a[2]), "r"(a[3]), "r"(b0), "r"(b1));
}
__device__ __forceinline__ void ldsm4(uint32_t* r, uint32_t saddr) {
    asm volatile("ldmatrix.sync.aligned.m8n8.x4.shared.b16 {%0,%1,%2,%3}, [%4];"
                 : "=r"(r[0]), "=r"(r[1]), "=r"(r[2]), "=r"(r[3]) : "r"(saddr));
}
__device__ __forceinline__ uint32_t s2u(const void* p) {
    uint32_t a;
    asm("{ .reg .u64 t; cvta.to.shared.u64 t, %1; cvt.u32.u64 %0, t; }"
        : "=r"(a) : "l"(p));
    return a;
}

// ---------------- small kernels ----------------
__global__ void copy_init_kernel(const float* __restrict__ cin) {
    int i = blockIdx.x * blockDim.x + threadIdx.x;
    if (i < GRP * KC * DIM) g_centroids[i] = cin[i];
}

__device__ __forceinline__ void emit_planes(int g, int k, int b, const float* src,
                                            float denom, int bad, float* out,
                                            bool writeback) {
    float s = 0.f;
    for (int pp = threadIdx.x; pp < KPADP; pp += 128) {
        int k0 = 2 * pp;
        float v0 = 0.f, v1 = 0.f;
        if (k0 < DIM) {
            v0 = bad ? 0.f : src[k0] / denom;
            if (writeback) {
                g_centroids[b * DIM + k0] = v0;
                if (out) out[b * DIM + k0] = v0;
                g_sums[b * DIM + k0] = 0.f;
            }
            s += v0 * v0;
        }
        if (k0 + 1 < DIM) {
            v1 = bad ? 0.f : src[k0 + 1] / denom;
            if (writeback) {
                g_centroids[b * DIM + k0 + 1] = v1;
                if (out) out[b * DIM + k0 + 1] = v1;
                g_sums[b * DIM + k0 + 1] = 0.f;
            }
            s += v1 * v1;
        }
        uint32_t h0, l0, h1, l1;
        split2h(v0, h0, l0);
        split2h(v1, h1, l1);
        g_cbp[g][0][k][pp] = pack2(h0, h1);
        g_cbp[g][1][k][pp] = pack2(l0, l1);
    }
#pragma unroll
    for (int o = 16; o; o >>= 1) s += __shfl_down_sync(0xffffffffu, s, o);
    __shared__ float ws[4];
    if ((threadIdx.x & 31) == 0) ws[threadIdx.x >> 5] = s;
    __syncthreads();
    if (threadIdx.x == 0) {
        g_c2[b] = 0.5f * (ws[0] + ws[1] + ws[2] + ws[3]);
        g_counts[b] = 0.f;
    }
}

__global__ void prep_kernel() {
    int b = blockIdx.x, g = b / KC, k = b % KC;
    for (int d = threadIdx.x; d < DIM; d += 128) g_sums[b * DIM + d] = 0.f;
    emit_planes(g, k, b, &g_centroids[b * DIM], 1.f, 0, nullptr, false);
}

__global__ void finalize_kernel(float* out) {
    int b = blockIdx.x, g = b / KC, k = b % KC;
    __shared__ float denom_s;
    __shared__ int bad_s;
    if (threadIdx.x == 0) {
        bool bad = false;
        for (int gg = 0; gg < GRP; gg++)
            if (g_counts[gg * KC + k] == 0.f) bad = true;
        float c = g_counts[b];
        denom_s = (c == 0.f) ? 1.f : c;
        bad_s = bad ? 1 : 0;
    }
    __syncthreads();
    emit_planes(g, k, b, &g_sums[b * DIM], denom_s, bad_s, out, true);
}

// ---- fused assign(fp16 3-term MMA, ldmatrix, TM=256, dbl-buffer) + sum ----
__global__ void __launch_bounds__(THREADS, 1) fused_kernel(const float* __restrict__ patches) {
    extern __shared__ float sm[];
    uint32_t* Apk = (uint32_t*)sm;                    // [2buf][2pl][256][APW]
    uint32_t* Bpk = (uint32_t*)sm + 2 * ABUFS;        // [2buf][2pl][64][APW]
    float* acc = sm + ACC_F;
    float* cnt = sm + CNT_F;
    int*   lbl = (int*)(sm + LBL_F);                  // [TM]
    float* c2s = sm + C2_F;

    const int tid = threadIdx.x;
    const int w = tid >> 5, lane = tid & 31;
    const int tq = lane & 3;
    const int mw = w;                      // 0..15: 16-row slab
    const int g = blockIdx.y;

    const int q8 = lane >> 3;
    const int r8 = lane & 7;

    const uint32_t sb = s2u(sm);
    const uint32_t A_base = sb;
    const uint32_t B_base = sb + 2 * ABUFS * 4;

    const uint32_t a_row_off = ((mw * 16 + (q8 & 1) * 8 + r8) * APW + (q8 >> 1) * 4) * 4;
    const uint32_t b_row_off0 = (((q8 >> 1) * 8 + r8) * APW + (q8 & 1) * 4) * 4;

    for (int i = tid; i < KC * DIM; i += THREADS) acc[i] = 0.f;
    if (tid < KC) { cnt[tid] = 0.f; c2s[tid] = g_c2[g * KC + tid]; }
    __syncthreads();

    for (int t = 0; ; t++) {
        const int tile = blockIdx.x + CTAS_X * t;
        if (tile >= TILES_G) break;
        const int row0 = tile * TM;
        const int nvalid = min(TM, N_PATCH - row0);
        const float* abase = patches + (size_t)row0 * ROWSTRIDE + g * DIM;

        float ac1[8][4], ac2[8][4];
#pragma unroll
        for (int j = 0; j < 8; j++)
#pragma unroll
            for (int q = 0; q < 4; q++) { ac1[j][q] = 0.f; ac2[j][q] = 0.f; }

        // prefetch chunk 0: 256 rows x 32 cols = 2048 float4
        float4 apf[4];
#pragma unroll
        for (int it = 0; it < 4; it++) {
            int idx = tid + it * THREADS;
            int r = idx >> 3, c4 = idx & 7;
            apf[it] = make_float4(0.f, 0.f, 0.f, 0.f);
            if (r < nvalid)
                apf[it] = *(const float4*)(abase + (size_t)r * ROWSTRIDE + c4 * 4);
        }

        for (int kc = 0; kc < NCH; kc++) {
            const int buf = kc & 1;
            uint32_t* Ab = Apk + buf * ABUFS;
            uint32_t* Bb = Bpk + buf * BBUFS;
            // store prefetched A as packed fp16 pairs, 2 planes
#pragma unroll
            for (int it = 0; it < 4; it++) {
                int idx = tid + it * THREADS;
                int r = idx >> 3, c4 = idx & 7;
                float4 v = apf[it];
                uint32_t h0,l0,h1,l1,h2,l2,h3,l3;
                split2h(v.x, h0, l0); split2h(v.y, h1, l1);
                split2h(v.z, h2, l2); split2h(v.w, h3, l3);
                uint32_t base = r * APW + 2 * c4;
                *(uint2*)&Ab[0 * APL2 + base] = make_uint2(pack2(h0, h1), pack2(h2, h3));
                *(uint2*)&Ab[1 * APL2 + base] = make_uint2(pack2(l0, l1), pack2(l2, l3));
            }
            // stage B chunk: 2 x 64 x 16 pairs = 512 uint4
            if (tid < 512) {
                int p = tid >> 8, e = tid & 255;
                int n = e >> 2, q = e & 3;
                uint4 v = *(const uint4*)&g_cbp[g][p][n][kc * 16 + q * 4];
                *(uint4*)&Bb[p * BPL2 + n * APW + q * 4] = v;
            }
            __syncthreads();   // chunk kc staged
            // prefetch next chunk (LDG hidden under MMA below)
            if (kc + 1 < NCH) {
                const int kn = (kc + 1) * 32;
#pragma unroll
                for (int it = 0; it < 4; it++) {
                    int idx = tid + it * THREADS;
                    int r = idx >> 3, c4 = idx & 7;
                    int col = kn + c4 * 4;
                    apf[it] = make_float4(0.f, 0.f, 0.f, 0.f);
                    if (r < nvalid && col < DIM)
                        apf[it] = *(const float4*)(abase + (size_t)r * ROWSTRIDE + col);
                }
            }
            // MMA on buf (2 k16-steps): warp covers 16 rows x 64 cols
            const uint32_t Abase = A_base + buf * ABUFS * 4;
            const uint32_t Bbase = B_base + buf * BBUFS * 4;
#pragma unroll
            for (int s = 0; s < 2; s++) {
                const uint32_t soff = (8 * s) * 4;
                uint32_t ah[4], al[4];
                ldsm4(ah, Abase + 0 * APL2 * 4 + a_row_off + soff);
                ldsm4(al, Abase + 1 * APL2 * 4 + a_row_off + soff);
#pragma unroll
                for (int jp = 0; jp < 4; jp++) {
                    const uint32_t joff = (jp * 16 * APW) * 4;
                    uint32_t bh[4], bl[4];
                    ldsm4(bh, Bbase + 0 * BPL2 * 4 + b_row_off0 + joff + soff);
                    ldsm4(bl, Bbase + 1 * BPL2 * 4 + b_row_off0 + joff + soff);
                    const int j0 = 2 * jp;
                    mma_f16(ac2[j0], al, bh[0], bh[1]);
                    mma_f16(ac2[j0], ah, bl[0], bl[1]);
                    mma_f16(ac1[j0], ah, bh[0], bh[1]);
                    mma_f16(ac2[j0 + 1], al, bh[2], bh[3]);
                    mma_f16(ac2[j0 + 1], ah, bl[2], bl[3]);
                    mma_f16(ac1[j0 + 1], ah, bh[2], bh[3]);
                }
            }
        }
        __syncthreads();   // all MMA fragment reads done before Cs overwrite

        // epilogue: combine accs -> Cs[256][65]
        float* Cs = sm;
        {
            const int tg = lane >> 2;
#pragma unroll
            for (int j = 0; j < 8; j++) {
                int c0 = j * 8 + 2 * tq;
                int rr = mw * 16 + tg;
                Cs[rr * 65 + c0]     = ac1[j][0] + LINV * ac2[j][0];
                Cs[rr * 65 + c0 + 1] = ac1[j][1] + LINV * ac2[j][1];
                Cs[(rr + 8) * 65 + c0]     = ac1[j][2] + LINV * ac2[j][2];
                Cs[(rr + 8) * 65 + c0 + 1] = ac1[j][3] + LINV * ac2[j][3];
            }
        }
        __syncthreads();

        // parallel argmax: 2 threads/row, 32 cols each, shfl merge (first-max)
        {
            int row = tid >> 1, seg = tid & 1;
            const float* r = &Cs[row * 65];
            int c0 = seg * 32;
            float best = r[c0] - c2s[c0];
            int bi = c0;
#pragma unroll
            for (int k2 = 1; k2 < 32; k2++) {
                float v = r[c0 + k2] - c2s[c0 + k2];
                if (v > best) { best = v; bi = c0 + k2; }
            }
            float vo = __shfl_xor_sync(0xffffffffu, best, 1);
            int   io = __shfl_xor_sync(0xffffffffu, bi, 1);
            if (vo > best || (vo == best && io < bi)) { best = vo; bi = io; }
            if (seg == 0 && row < nvalid) lbl[row] = bi;
        }
        __syncthreads();

        // accumulate: re-read tile rows (L2-hot) into smem accumulator
        const bool col_ok = (tid < DIM);
        for (int pb = 0; pb < nvalid; pb += 8) {
            int nu = min(8, nvalid - pb);
            int   l[8];
            float v0[8];
#pragma unroll
            for (int u = 0; u < 8; u++) {
                bool ok = (u < nu);
                int pp = ok ? (pb + u) : 0;
                l[u] = lbl[pp];
                v0[u] = (ok && col_ok) ? abase[(size_t)pp * ROWSTRIDE + tid] : 0.f;
            }
#pragma unroll
            for (int u = 0; u < 8; u++) {
                if (u < nu && col_ok) acc[l[u] * DIM + tid] += v0[u];
            }
        }
        if (tid < nvalid) atomicAdd(&cnt[lbl[tid]], 1.f);
        __syncthreads();
    }

    // flush accumulator + counts (once per persistent CTA)
    for (int i = tid * 4; i < KC * DIM; i += THREADS * 4) {
        float4 v = *(const float4*)&acc[i];
        float* dst = &g_sums[(size_t)g * KC * DIM + i];
        asm volatile("red.global.add.v4.f32 [%0], {%1, %2, %3, %4};"
                     :: "l"(dst), "f"(v.x), "f"(v.y), "f"(v.z), "f"(v.w)
                     : "memory");
    }
    if (tid < KC) atomicAdd(&g_counts[g * KC + tid], cnt[tid]);
}

// ---------------- launch ----------------
extern "C" void kernel_launch(void* const* d_in, const int* in_sizes, int n_in,
                              void* d_out, int out_size) {
    const float* patches = (const float*)d_in[0];
    const float* cinit   = (const float*)d_in[1];
    float* out = (float*)d_out;

    cudaFuncSetAttribute(fused_kernel, cudaFuncAttributeMaxDynamicSharedMemorySize, FUSED_SMEM);

    copy_init_kernel<<<(GRP * KC * DIM + 255) / 256, 256>>>(cinit);
    prep_kernel<<<GRP * KC, 128>>>();

    for (int e = 0; e < EPOCHS; e++) {
        fused_kernel<<<dim3(CTAS_X, GRP), THREADS, FUSED_SMEM>>>(patches);
        finalize_kernel<<<GRP * KC, 128>>>(e == EPOCHS - 1 ? out : nullptr);
    }
}

// round 17
// speedup vs baseline: 1.1727x; 1.1727x over previous
#include <cuda_runtime.h>
#include <cuda_fp16.h>
#include <stdint.h>

// ---------------- problem constants ----------------
#define N_PATCH   40000
#define GRP       4
#define DIM       400          // 16*5*5
#define KC        64
#define EPOCHS    10
#define ROWSTRIDE 1600         // GRP*DIM floats per patch row
#define TM        128          // patches per tile (MMA M)
#define KPADP     208          // K padded to 416 = 208 fp16-pairs
#define NCH       13           // chunks of 32 k (16 pairs)
#define TILES_G   313
#define XCTAS     37           // CTAs per group; total 148 = 1 CTA/SM
#define NCTAS     148
#define THREADS   512
#define LSCALE    2048.0f      // low-plane scale 2^11
#define LINV      4.8828125e-4f

// fused-kernel smem layout (double-buffered staging)
#define APW    20              // pair-slots per row (16 + 4 pad) in uint32
#define APL2   (128*APW)       // 2560 u32 per A plane
#define BPL2   (64*APW)        // 1280 u32 per B plane
#define ABUFS  (2*APL2)
#define BBUFS  (2*BPL2)
#define STG_F  (2*ABUFS + 2*BBUFS)     // 15360 u32 (>= Cs 128*65=8320)
#define ACC_F  STG_F
#define CNT_F  (ACC_F + KC*DIM)        // 40960 (also finalize scratch)
#define LBL_F  (CNT_F + KC)            // 41024
#define C2_F   (LBL_F + TM)            // 41152
#define FUSED_F (C2_F + KC)            // 41216 floats
#define FUSED_SMEM (FUSED_F * 4)       // 164,864 B -> 1 CTA/SM

// ---------------- device state ----------------
__device__ float g_centroids[GRP * KC * DIM];
__device__ float g_c2[GRP * KC];
__device__ __align__(16) float g_sums[GRP * KC * DIM];
__device__ float g_counts2[2][GRP * KC];         // epoch-parity double buffer
__device__ __align__(16) uint32_t g_cbp[GRP][2][KC][KPADP];
__device__ volatile unsigned int g_bar;          // grid barrier counter

// ---------------- fp16 split helpers ----------------
__device__ __forceinline__ void split2h(float x, uint32_t& h, uint32_t& l) {
    __half hh = __float2half_rn(x);
    float r = x - __half2float(hh);
    __half ll = __float2half_rn(r * LSCALE);
    h = (uint32_t)__half_as_ushort(hh);
    l = (uint32_t)__half_as_ushort(ll);
}
__device__ __forceinline__ uint32_t pack2(uint32_t a, uint32_t b) {
    return a | (b << 16);
}
__device__ __forceinline__ void mma_f16(float* c, const uint32_t* a,
                                        uint32_t b0, uint32_t b1) {
    asm volatile(
        "mma.sync.aligned.m16n8k16.row.col.f32.f16.f16.f32 "
        "{%0,%1,%2,%3}, {%4,%5,%6,%7}, {%8,%9}, {%0,%1,%2,%3};"
        : "+f"(c[0]), "+f"(c[1]), "+f"(c[2]), "+f"(c[3])
        : "r"(a[0]), "r"(a[1]), "r"(a[2]), "r"(a[3]), "r"(b0), "r"(b1));
}
__device__ __forceinline__ void ldsm4(uint32_t* r, uint32_t saddr) {
    asm volatile("ldmatrix.sync.aligned.m8n8.x4.shared.b16 {%0,%1,%2,%3}, [%4];"
                 : "=r"(r[0]), "=r"(r[1]), "=r"(r[2]), "=r"(r[3]) : "r"(saddr));
}
__device__ __forceinline__ uint32_t s2u(const void* p) {
    uint32_t a;
    asm("{ .reg .u64 t; cvta.to.shared.u64 t, %1; cvt.u32.u64 %0, t; }"
        : "=r"(a) : "l"(p));
    return a;
}
__device__ __forceinline__ uint4 ldcg4(const uint32_t* p) {
    uint4 v;
    asm volatile("ld.global.cg.v4.u32 {%0,%1,%2,%3}, [%4];"
                 : "=r"(v.x), "=r"(v.y), "=r"(v.z), "=r"(v.w) : "l"(p));
    return v;
}
__device__ __forceinline__ float ldcgf(const float* p) {
    float v;
    asm volatile("ld.global.cg.f32 %0, [%1];" : "=f"(v) : "l"(p));
    return v;
}

// ---------------- setup kernels ----------------
__global__ void copy_init_kernel(const float* __restrict__ cin) {
    int i = blockIdx.x * blockDim.x + threadIdx.x;
    if (i < GRP * KC * DIM) g_centroids[i] = cin[i];
    if (i == 0) g_bar = 0;
    if (i < 2 * GRP * KC) ((float*)g_counts2)[i] = 0.f;
}

// epoch-0 prep (128 threads/block): split planes + c2 + zero sums
__global__ void prep_kernel() {
    int b = blockIdx.x, g = b / KC, k = b % KC;
    const float* src = &g_centroids[b * DIM];
    float s = 0.f;
    for (int pp = threadIdx.x; pp < KPADP; pp += 128) {
        int k0 = 2 * pp;
        float v0 = (k0 < DIM) ? src[k0] : 0.f;
        float v1 = (k0 + 1 < DIM) ? src[k0 + 1] : 0.f;
        if (k0 < DIM) g_sums[b * DIM + k0] = 0.f;
        if (k0 + 1 < DIM) g_sums[b * DIM + k0 + 1] = 0.f;
        s += v0 * v0 + v1 * v1;
        uint32_t h0, l0, h1, l1;
        split2h(v0, h0, l0);
        split2h(v1, h1, l1);
        g_cbp[g][0][k][pp] = pack2(h0, h1);
        g_cbp[g][1][k][pp] = pack2(l0, l1);
    }
#pragma unroll
    for (int o = 16; o; o >>= 1) s += __shfl_down_sync(0xffffffffu, s, o);
    __shared__ float ws[4];
    if ((threadIdx.x & 31) == 0) ws[threadIdx.x >> 5] = s;
    __syncthreads();
    if (threadIdx.x == 0) g_c2[b] = 0.5f * (ws[0] + ws[1] + ws[2] + ws[3]);
}

// ---------------- THE persistent kernel: all 10 epochs ----------------
__global__ void __launch_bounds__(THREADS, 1) persist_kernel(
        const float* __restrict__ patches, float* __restrict__ out) {
    extern __shared__ float sm[];
    uint32_t* Apk = (uint32_t*)sm;                    // [2buf][2pl][128][APW]
    uint32_t* Bpk = (uint32_t*)sm + 2 * ABUFS;
    float* acc = sm + ACC_F;
    float* cnt = sm + CNT_F;                          // also finalize scratch
    int*   lbl = (int*)(sm + LBL_F);
    float* c2s = sm + C2_F;

    const int tid = threadIdx.x;
    const int w = tid >> 5, lane = tid & 31;
    const int tq = lane & 3;
    const int mw = w >> 1;
    const int nh = w & 1;
    const int g = blockIdx.x & 3;
    const int x = blockIdx.x >> 2;                    // 0..36

    const int q8 = lane >> 3;
    const int r8 = lane & 7;

    const uint32_t sb = s2u(sm);
    const uint32_t A_base = sb;
    const uint32_t B_base = sb + 2 * ABUFS * 4;
    const uint32_t a_row_off = ((mw * 16 + (q8 & 1) * 8 + r8) * APW + (q8 >> 1) * 4) * 4;
    const uint32_t b_row_off0 = ((nh * 32 + (q8 >> 1) * 8 + r8) * APW + (q8 & 1) * 4) * 4;
    const bool col_ok = (tid < DIM);

    unsigned int bar_target = 0;

    for (int e = 0; e < EPOCHS; e++) {
        // epoch init: load c2, zero acc + cnt
        for (int i = tid; i < KC * DIM; i += THREADS) acc[i] = 0.f;
        if (tid < KC) { cnt[tid] = 0.f; c2s[tid] = ldcgf(&g_c2[g * KC + tid]); }
        __syncthreads();

        // ---- tile loop (R14-proven body) ----
        for (int t = 0; ; t++) {
            const int tile = x + XCTAS * t;
            if (tile >= TILES_G) break;
            const int row0 = tile * TM;
            const int nvalid = min(TM, N_PATCH - row0);
            const float* abase = patches + (size_t)row0 * ROWSTRIDE + g * DIM;

            float ac1[4][4], ac2[4][4];
#pragma unroll
            for (int j = 0; j < 4; j++)
#pragma unroll
                for (int q = 0; q < 4; q++) { ac1[j][q] = 0.f; ac2[j][q] = 0.f; }

            float4 apf[2];
#pragma unroll
            for (int it = 0; it < 2; it++) {
                int idx = tid + it * THREADS;
                int r = idx >> 3, c4 = idx & 7;
                apf[it] = make_float4(0.f, 0.f, 0.f, 0.f);
                if (r < nvalid)
                    apf[it] = *(const float4*)(abase + (size_t)r * ROWSTRIDE + c4 * 4);
            }

            for (int kc = 0; kc < NCH; kc++) {
                const int buf = kc & 1;
                uint32_t* Ab = Apk + buf * ABUFS;
                uint32_t* Bb = Bpk + buf * BBUFS;
#pragma unroll
                for (int it = 0; it < 2; it++) {
                    int idx = tid + it * THREADS;
                    int r = idx >> 3, c4 = idx & 7;
                    float4 v = apf[it];
                    uint32_t h0,l0,h1,l1,h2,l2,h3,l3;
                    split2h(v.x, h0, l0); split2h(v.y, h1, l1);
                    split2h(v.z, h2, l2); split2h(v.w, h3, l3);
                    uint32_t base = r * APW + 2 * c4;
                    *(uint2*)&Ab[0 * APL2 + base] = make_uint2(pack2(h0, h1), pack2(h2, h3));
                    *(uint2*)&Ab[1 * APL2 + base] = make_uint2(pack2(l0, l1), pack2(l2, l3));
                }
                if (tid < 512) {
                    int p = tid >> 8, ee = tid & 255;
                    int n = ee >> 2, q = ee & 3;
                    uint4 v = ldcg4(&g_cbp[g][p][n][kc * 16 + q * 4]);
                    *(uint4*)&Bb[p * BPL2 + n * APW + q * 4] = v;
                }
                __syncthreads();
                if (kc + 1 < NCH) {
                    const int kn = (kc + 1) * 32;
#pragma unroll
                    for (int it = 0; it < 2; it++) {
                        int idx = tid + it * THREADS;
                        int r = idx >> 3, c4 = idx & 7;
                        int col = kn + c4 * 4;
                        apf[it] = make_float4(0.f, 0.f, 0.f, 0.f);
                        if (r < nvalid && col < DIM)
                            apf[it] = *(const float4*)(abase + (size_t)r * ROWSTRIDE + col);
                    }
                }
                const uint32_t Abase = A_base + buf * ABUFS * 4;
                const uint32_t Bbase = B_base + buf * BBUFS * 4;
#pragma unroll
                for (int s = 0; s < 2; s++) {
                    const uint32_t soff = (8 * s) * 4;
                    uint32_t ah[4], al[4];
                    ldsm4(ah, Abase + 0 * APL2 * 4 + a_row_off + soff);
                    ldsm4(al, Abase + 1 * APL2 * 4 + a_row_off + soff);
#pragma unroll
                    for (int jp = 0; jp < 2; jp++) {
                        const uint32_t joff = (jp * 16 * APW) * 4;
                        uint32_t bh[4], bl[4];
                        ldsm4(bh, Bbase + 0 * BPL2 * 4 + b_row_off0 + joff + soff);
                        ldsm4(bl, Bbase + 1 * BPL2 * 4 + b_row_off0 + joff + soff);
                        const int j0 = 2 * jp;
                        mma_f16(ac2[j0], al, bh[0], bh[1]);
                        mma_f16(ac2[j0], ah, bl[0], bl[1]);
                        mma_f16(ac1[j0], ah, bh[0], bh[1]);
                        mma_f16(ac2[j0 + 1], al, bh[2], bh[3]);
                        mma_f16(ac2[j0 + 1], ah, bl[2], bl[3]);
                        mma_f16(ac1[j0 + 1], ah, bh[2], bh[3]);
                    }
                }
            }
            __syncthreads();

            float* Cs = sm;
            {
                const int tg = lane >> 2;
#pragma unroll
                for (int j = 0; j < 4; j++) {
                    int c0 = nh * 32 + j * 8 + 2 * tq;
                    int rr = mw * 16 + tg;
                    Cs[rr * 65 + c0]     = ac1[j][0] + LINV * ac2[j][0];
                    Cs[rr * 65 + c0 + 1] = ac1[j][1] + LINV * ac2[j][1];
                    Cs[(rr + 8) * 65 + c0]     = ac1[j][2] + LINV * ac2[j][2];
                    Cs[(rr + 8) * 65 + c0 + 1] = ac1[j][3] + LINV * ac2[j][3];
                }
            }
            __syncthreads();

            {
                int row = tid >> 2, seg = tid & 3;
                const float* r = &Cs[row * 65];
                int c0 = seg * 16;
                float best = r[c0] - c2s[c0];
                int bi = c0;
#pragma unroll
                for (int k2 = 1; k2 < 16; k2++) {
                    float v = r[c0 + k2] - c2s[c0 + k2];
                    if (v > best) { best = v; bi = c0 + k2; }
                }
#pragma unroll
                for (int o = 1; o < 4; o <<= 1) {
                    float vo = __shfl_xor_sync(0xffffffffu, best, o);
                    int   io = __shfl_xor_sync(0xffffffffu, bi, o);
                    if (vo > best || (vo == best && io < bi)) { best = vo; bi = io; }
                }
                if (seg == 0 && row < nvalid) lbl[row] = bi;
            }
            __syncthreads();

            for (int pb = 0; pb < nvalid; pb += 8) {
                int nu = min(8, nvalid - pb);
                int   l[8];
                float v0[8];
#pragma unroll
                for (int u = 0; u < 8; u++) {
                    bool ok = (u < nu);
                    int pp = ok ? (pb + u) : 0;
                    l[u] = lbl[pp];
                    v0[u] = (ok && col_ok) ? abase[(size_t)pp * ROWSTRIDE + tid] : 0.f;
                }
#pragma unroll
                for (int u = 0; u < 8; u++) {
                    if (u < nu && col_ok) acc[l[u] * DIM + tid] += v0[u];
                }
            }
            if (tid < nvalid) atomicAdd(&cnt[lbl[tid]], 1.f);
            __syncthreads();
        }

        // ---- flush ----
        for (int i = tid * 4; i < KC * DIM; i += THREADS * 4) {
            float4 v = *(const float4*)&acc[i];
            float* dst = &g_sums[(size_t)g * KC * DIM + i];
            asm volatile("red.global.add.v4.f32 [%0], {%1, %2, %3, %4};"
                         :: "l"(dst), "f"(v.x), "f"(v.y), "f"(v.z), "f"(v.w)
                         : "memory");
        }
        if (tid < KC) atomicAdd(&g_counts2[e & 1][g * KC + tid], cnt[tid]);

        // ---- grid sync 1 ----
        __syncthreads();
        if (tid == 0) {
            __threadfence();
            atomicAdd((unsigned int*)&g_bar, 1u);
            bar_target += NCTAS;
            while (g_bar < bar_target) __nanosleep(64);
            __threadfence();
        }
        __syncthreads();
        bar_target = (e * 2 + 1) * NCTAS;   // keep all threads' view consistent

        // ---- finalize jobs (b = cta, cta+148) ----
        const float* cbuf = g_counts2[e & 1];
        for (int b = blockIdx.x; b < GRP * KC; b += NCTAS) {
            int jg = b >> 6, jk = b & 63;
            if (tid == 0) {
                bool bad = false;
                for (int gg = 0; gg < GRP; gg++)
                    if (ldcgf(&cbuf[gg * KC + jk]) == 0.f) bad = true;
                float c = ldcgf(&cbuf[b]);
                cnt[16] = (c == 0.f) ? 1.f : c;
                cnt[17] = bad ? 1.f : 0.f;
            }
            __syncthreads();
            float denom = cnt[16];
            int bad = (cnt[17] != 0.f);
            float s = 0.f;
            for (int pp = tid; pp < KPADP; pp += THREADS) {
                int k0 = 2 * pp;
                float v0 = 0.f, v1 = 0.f;
                if (k0 < DIM) {
                    v0 = bad ? 0.f : ldcgf(&g_sums[b * DIM + k0]) / denom;
                    g_centroids[b * DIM + k0] = v0;
                    if (e == EPOCHS - 1) out[b * DIM + k0] = v0;
                    g_sums[b * DIM + k0] = 0.f;
                    s += v0 * v0;
                }
                if (k0 + 1 < DIM) {
                    v1 = bad ? 0.f : ldcgf(&g_sums[b * DIM + k0 + 1]) / denom;
                    g_centroids[b * DIM + k0 + 1] = v1;
                    if (e == EPOCHS - 1) out[b * DIM + k0 + 1] = v1;
                    g_sums[b * DIM + k0 + 1] = 0.f;
                    s += v1 * v1;
                }
                uint32_t h0, l0, h1, l1;
                split2h(v0, h0, l0);
                split2h(v1, h1, l1);
                g_cbp[jg][0][jk][pp] = pack2(h0, h1);
                g_cbp[jg][1][jk][pp] = pack2(l0, l1);
            }
#pragma unroll
            for (int o = 16; o; o >>= 1) s += __shfl_down_sync(0xffffffffu, s, o);
            if (lane == 0) cnt[32 + w] = s;
            __syncthreads();
            if (tid == 0) {
                float tot = 0.f;
                for (int i = 0; i < 16; i++) tot += cnt[32 + i];
                g_c2[b] = 0.5f * tot;
                g_counts2[(e + 1) & 1][b] = 0.f;   // zero next-epoch buffer
            }
            __syncthreads();
        }

        // ---- grid sync 2 ----
        __syncthreads();
        if (tid == 0) {
            __threadfence();
            atomicAdd((unsigned int*)&g_bar, 1u);
            unsigned int tgt = (unsigned int)(e * 2 + 2) * NCTAS;
            while (g_bar < tgt) __nanosleep(64);
            __threadfence();
        }
        __syncthreads();
        bar_target = (unsigned int)(e * 2 + 2) * NCTAS;
    }
}

// ---------------- launch ----------------
extern "C" void kernel_launch(void* const* d_in, const int* in_sizes, int n_in,
                              void* d_out, int out_size) {
    const float* patches = (const float*)d_in[0];
    const float* cinit   = (const float*)d_in[1];
    float* out = (float*)d_out;

    cudaFuncSetAttribute(persist_kernel, cudaFuncAttributeMaxDynamicSharedMemorySize, FUSED_SMEM);

    copy_init_kernel<<<(GRP * KC * DIM + 255) / 256, 256>>>(cinit);
    prep_kernel<<<GRP * KC, 128>>>();
    persist_kernel<<<NCTAS, THREADS, FUSED_SMEM>>>(patches, out);
}